// round 4
// baseline (speedup 1.0000x reference)
#include <cuda_runtime.h>
#include <cuda_bf16.h>
#include <cstdint>

#define DD 2048
#define BB 256
#define TT 64

// scratch (static device array — no allocations)
__device__ float g_u[BB * DD];   // 2 MB: u = E@(W-I) + E + hb

// ---------------------------------------------------------------------------
// mma / ldmatrix helpers
// ---------------------------------------------------------------------------
__device__ __forceinline__ void mma16816(float* d, const uint32_t* a,
                                         uint32_t b0, uint32_t b1)
{
    asm volatile(
        "mma.sync.aligned.m16n8k16.row.col.f32.bf16.bf16.f32 "
        "{%0,%1,%2,%3}, {%4,%5,%6,%7}, {%8,%9}, {%0,%1,%2,%3};\n"
        : "+f"(d[0]), "+f"(d[1]), "+f"(d[2]), "+f"(d[3])
        : "r"(a[0]), "r"(a[1]), "r"(a[2]), "r"(a[3]), "r"(b0), "r"(b1));
}
__device__ __forceinline__ void ldsm_x4(uint32_t* r, uint32_t addr)
{
    asm volatile("ldmatrix.sync.aligned.m8n8.x4.shared.b16 {%0,%1,%2,%3}, [%4];\n"
                 : "=r"(r[0]), "=r"(r[1]), "=r"(r[2]), "=r"(r[3]) : "r"(addr));
}
__device__ __forceinline__ void ldsm_x4_t(uint32_t* r, uint32_t addr)
{
    asm volatile("ldmatrix.sync.aligned.m8n8.x4.trans.shared.b16 {%0,%1,%2,%3}, [%4];\n"
                 : "=r"(r[0]), "=r"(r[1]), "=r"(r[2]), "=r"(r[3]) : "r"(addr));
}

__device__ __forceinline__ uint4 pack_bf16x8(const float4& a, const float4& b)
{
    __nv_bfloat162 p0 = __floats2bfloat162_rn(a.x, a.y);
    __nv_bfloat162 p1 = __floats2bfloat162_rn(a.z, a.w);
    __nv_bfloat162 p2 = __floats2bfloat162_rn(b.x, b.y);
    __nv_bfloat162 p3 = __floats2bfloat162_rn(b.z, b.w);
    uint4 o;
    o.x = *reinterpret_cast<uint32_t*>(&p0);
    o.y = *reinterpret_cast<uint32_t*>(&p1);
    o.z = *reinterpret_cast<uint32_t*>(&p2);
    o.w = *reinterpret_cast<uint32_t*>(&p3);
    return o;
}

// ---------------------------------------------------------------------------
// Fused GEMM: U = bf16(E) @ bf16(W - I) + E + hb
// BM=BN=BK=64, 256 threads. fp32 tiles loaded reg-pipelined (LDG.128),
// converted to bf16 in registers, STS.128 into swizzled smem, mma.m16n8k16.
// Diagonal -1 applied during the B-tile convert; identity added exactly
// (in fp32) in the epilogue, so bf16 never rounds the O(1) diagonal.
// ---------------------------------------------------------------------------
__global__ __launch_bounds__(256) void gemm_u_kernel(
    const float* __restrict__ E, const float* __restrict__ W,
    const float* __restrict__ hb)
{
    __shared__ __align__(1024) __nv_bfloat16 As[2][64 * 64];
    __shared__ __align__(1024) __nv_bfloat16 Bs[2][64 * 64];

    const int tid  = threadIdx.x;
    const int lane = tid & 31;
    const int wid  = tid >> 5;
    const int wm   = (wid >> 2) << 5;   // 0 / 32
    const int wn   = (wid & 3) << 4;    // 0,16,32,48
    const int bm   = blockIdx.y << 6;
    const int bn   = blockIdx.x << 6;

    float acc[2][2][4];
    #pragma unroll
    for (int i = 0; i < 2; i++)
        #pragma unroll
        for (int j = 0; j < 2; j++)
            #pragma unroll
            for (int k = 0; k < 4; k++) acc[i][j][k] = 0.f;

    // load mapping: pair p covers 8 consecutive floats (2 float4 -> 1 bf16 uint4)
    // p in {tid, tid+256}; row = p>>3 (0..63 over the two), c = p&7
    const int row0 = tid >> 3;          // 0..31; second pair row0+32
    const int c0   = tid & 7;           // 8-float chunk within 64-wide row

    const float* gA0 = E + (size_t)(bm + row0) * DD + c0 * 8;
    const float* gA1 = gA0 + (size_t)32 * DD;
    const float* gB0 = W + (size_t)row0 * DD + bn + c0 * 8;
    const float* gB1 = gB0 + (size_t)32 * DD;

    // swizzled 16B-chunk offsets for the bf16 tiles (row<<7 | (c^(row&7))<<4)
    const uint32_t offR0 = (uint32_t)((row0 << 7) + ((c0 ^ (row0 & 7)) << 4));
    const uint32_t offR1 = offR0 + (32 << 7);   // row0+32 keeps (row&7)

    uint32_t sA[2], sB[2];
    sA[0] = (uint32_t)__cvta_generic_to_shared(&As[0][0]);
    sA[1] = (uint32_t)__cvta_generic_to_shared(&As[1][0]);
    sB[0] = (uint32_t)__cvta_generic_to_shared(&Bs[0][0]);
    sB[1] = (uint32_t)__cvta_generic_to_shared(&Bs[1][0]);

    // ldmatrix addressing (same validated scheme as before)
    const int l15 = lane & 15;
    const int l7  = lane & 7;
    const int kcB = lane >> 4;
    uint32_t aRow[2];
    #pragma unroll
    for (int im = 0; im < 2; im++) aRow[im] = (uint32_t)((wm + im * 16 + l15) << 7);
    const int nChunkBase = wn >> 3;

    float4 ra[2][2], rb[2][2];   // [pair][half]

    #define LOAD_REGS(k0)                                                   \
        {                                                                   \
            ra[0][0] = *reinterpret_cast<const float4*>(gA0 + (k0));        \
            ra[0][1] = *reinterpret_cast<const float4*>(gA0 + (k0) + 4);    \
            ra[1][0] = *reinterpret_cast<const float4*>(gA1 + (k0));        \
            ra[1][1] = *reinterpret_cast<const float4*>(gA1 + (k0) + 4);    \
            rb[0][0] = *reinterpret_cast<const float4*>(gB0 + (size_t)(k0) * DD);     \
            rb[0][1] = *reinterpret_cast<const float4*>(gB0 + (size_t)(k0) * DD + 4); \
            rb[1][0] = *reinterpret_cast<const float4*>(gB1 + (size_t)(k0) * DD);     \
            rb[1][1] = *reinterpret_cast<const float4*>(gB1 + (size_t)(k0) * DD + 4); \
        }

    LOAD_REGS(0);

    const int NIT = DD / 64;   // 32
    for (int it = 0; it < NIT; it++) {
        const int s  = it & 1;
        const int k0 = it * 64;

        // convert + store current regs to bf16 smem (diag fix on B)
        {
            // B pair 0: global row k0+row0, cols bn + c0*8 + [0,8)
            int d0 = (k0 + row0) - (bn + c0 * 8);
            float4 b00 = rb[0][0], b01 = rb[0][1];
            if (d0 >= 0 && d0 < 4)      reinterpret_cast<float*>(&b00)[d0]     -= 1.0f;
            else if (d0 >= 4 && d0 < 8) reinterpret_cast<float*>(&b01)[d0 - 4] -= 1.0f;
            int d1 = d0 + 32;           // global row k0+row0+32
            float4 b10 = rb[1][0], b11 = rb[1][1];
            if (d1 >= 0 && d1 < 4)      reinterpret_cast<float*>(&b10)[d1]     -= 1.0f;
            else if (d1 >= 4 && d1 < 8) reinterpret_cast<float*>(&b11)[d1 - 4] -= 1.0f;

            uint4 pa0 = pack_bf16x8(ra[0][0], ra[0][1]);
            uint4 pa1 = pack_bf16x8(ra[1][0], ra[1][1]);
            uint4 pb0 = pack_bf16x8(b00, b01);
            uint4 pb1 = pack_bf16x8(b10, b11);
            asm volatile("st.shared.v4.b32 [%0], {%1,%2,%3,%4};\n"
                         :: "r"(sA[s] + offR0), "r"(pa0.x), "r"(pa0.y), "r"(pa0.z), "r"(pa0.w));
            asm volatile("st.shared.v4.b32 [%0], {%1,%2,%3,%4};\n"
                         :: "r"(sA[s] + offR1), "r"(pa1.x), "r"(pa1.y), "r"(pa1.z), "r"(pa1.w));
            asm volatile("st.shared.v4.b32 [%0], {%1,%2,%3,%4};\n"
                         :: "r"(sB[s] + offR0), "r"(pb0.x), "r"(pb0.y), "r"(pb0.z), "r"(pb0.w));
            asm volatile("st.shared.v4.b32 [%0], {%1,%2,%3,%4};\n"
                         :: "r"(sB[s] + offR1), "r"(pb1.x), "r"(pb1.y), "r"(pb1.z), "r"(pb1.w));
        }

        // prefetch next tile into registers (overlaps with mma below)
        if (it + 1 < NIT) LOAD_REGS(k0 + 64);

        __syncthreads();

        #pragma unroll
        for (int kk = 0; kk < 4; kk++) {
            uint32_t a[2][4], b[4];
            const int kchunk = kk * 2 + kcB;
            #pragma unroll
            for (int im = 0; im < 2; im++)
                ldsm_x4(a[im], sA[s] + aRow[im] + (uint32_t)((kchunk ^ l7) << 4));
            {
                const int krow = kk * 16 + l15;
                const int nchunk = nChunkBase + kcB;
                ldsm_x4_t(b, sB[s] + (uint32_t)(krow << 7)
                               + (uint32_t)((nchunk ^ (krow & 7)) << 4));
            }
            #pragma unroll
            for (int im = 0; im < 2; im++) {
                mma16816(acc[im][0], a[im], b[0], b[1]);
                mma16816(acc[im][1], a[im], b[2], b[3]);
            }
        }
        // no trailing barrier: double buffering + next iteration's barrier
        // separate this iteration's ldmatrix reads from the it+2 STS writes
    }
    #undef LOAD_REGS

    // epilogue: u = acc + E (exact identity part) + hb
    #pragma unroll
    for (int im = 0; im < 2; im++) {
        const int row0e = bm + wm + im * 16 + (lane >> 2);
        #pragma unroll
        for (int in = 0; in < 2; in++) {
            const int col = bn + wn + in * 8 + ((lane & 3) << 1);
            const float h0 = hb[col], h1 = hb[col + 1];
            g_u[(size_t)row0e * DD + col]
                = acc[im][in][0] + E[(size_t)row0e * DD + col] + h0;
            g_u[(size_t)row0e * DD + col + 1]
                = acc[im][in][1] + E[(size_t)row0e * DD + col + 1] + h1;
            g_u[(size_t)(row0e + 8) * DD + col]
                = acc[im][in][2] + E[(size_t)(row0e + 8) * DD + col] + h0;
            g_u[(size_t)(row0e + 8) * DD + col + 1]
                = acc[im][in][3] + E[(size_t)(row0e + 8) * DD + col + 1] + h1;
        }
    }
}

// ---------------------------------------------------------------------------
// Kernel B: scoring (unchanged from round-3 winner). grid (256,2), 512 thr.
// ---------------------------------------------------------------------------
__global__ __launch_bounds__(512) void score_kernel(
    const float* __restrict__ E,
    const float* __restrict__ theo,
    const float* __restrict__ cand,
    const float* __restrict__ vb,
    float* __restrict__ out)
{
    const int b    = blockIdx.x;
    const int tc   = blockIdx.y;       // 0..1
    const int tid  = threadIdx.x;
    const int lane = tid & 31;
    const int wid  = tid >> 5;         // 0..15

    __shared__ float u_s[DD];
    __shared__ float red[32];
    __shared__ float s_vb, s_pos;

    float pv, pp = 0.f;
    {
        const int i = tid * 4;
        float4 u4 = *reinterpret_cast<const float4*>(&g_u[(size_t)b * DD + i]);
        *reinterpret_cast<float4*>(&u_s[i]) = u4;
        float4 e4 = *reinterpret_cast<const float4*>(&E[(size_t)b * DD + i]);
        float4 v4 = *reinterpret_cast<const float4*>(&vb[i]);
        pv = e4.x * v4.x + e4.y * v4.y + e4.z * v4.z + e4.w * v4.w;
        if (tc == 0) {
            float4 c4 = *reinterpret_cast<const float4*>(&cand[(size_t)b * DD + i]);
            pp = u4.x * c4.x + u4.y * c4.y + u4.z * c4.z + u4.w * c4.w;
        }
    }
    #pragma unroll
    for (int o = 16; o > 0; o >>= 1) {
        pv += __shfl_xor_sync(0xFFFFFFFFu, pv, o);
        pp += __shfl_xor_sync(0xFFFFFFFFu, pp, o);
    }
    if (lane == 0) { red[wid] = pv; red[16 + wid] = pp; }
    __syncthreads();
    if (tid == 0) {
        float v = 0.f, p = 0.f;
        #pragma unroll
        for (int w = 0; w < 16; w++) { v += red[w]; p += red[16 + w]; }
        s_vb  = v;
        s_pos = p + v;
    }
    __syncthreads();
    const float vbb = s_vb;

    const int t0 = tc * 32 + wid * 2;
    const float4* ra  = reinterpret_cast<const float4*>(&theo[((size_t)b * TT + t0) * DD]);
    const float4* rb  = ra + DD / 4;
    const float4* u4p = reinterpret_cast<const float4*>(u_s);

    float s0 = 0.f, s1 = 0.f;
    #pragma unroll 4
    for (int i = lane; i < DD / 4; i += 32) {
        float4 x = __ldcs(&ra[i]);
        float4 y = __ldcs(&rb[i]);
        float4 u = u4p[i];
        s0 += x.x * u.x + x.y * u.y + x.z * u.z + x.w * u.w;
        s1 += y.x * u.x + y.y * u.y + y.z * u.z + y.w * u.w;
    }
    #pragma unroll
    for (int o = 16; o > 0; o >>= 1) {
        s0 += __shfl_xor_sync(0xFFFFFFFFu, s0, o);
        s1 += __shfl_xor_sync(0xFFFFFFFFu, s1, o);
    }
    if (lane == 0) {
        out[b * (TT + 1) + 1 + t0]     = s0 + vbb;
        out[b * (TT + 1) + 1 + t0 + 1] = s1 + vbb;
    }
    if (tc == 0 && tid == 0) out[b * (TT + 1)] = s_pos;
}

// ---------------------------------------------------------------------------
// launch: 0=experimental [B,D], 1=theoretical [B,T,D], 2=candidate [B,D],
//         3=W [D,D], 4=vb [D], 5=hb [D] ; out fp32 [B, 1+T]
// ---------------------------------------------------------------------------
extern "C" void kernel_launch(void* const* d_in, const int* in_sizes, int n_in,
                              void* d_out, int out_size)
{
    const float* E    = (const float*)d_in[0];
    const float* theo = (const float*)d_in[1];
    const float* cand = (const float*)d_in[2];
    const float* W    = (const float*)d_in[3];
    const float* vb   = (const float*)d_in[4];
    const float* hb   = (const float*)d_in[5];
    float*       out  = (float*)d_out;

    gemm_u_kernel<<<dim3(DD / 64, BB / 64), 256>>>(E, W, hb);
    score_kernel<<<dim3(BB, 2), 512>>>(E, theo, cand, vb, out);
}

// round 5
// speedup vs baseline: 1.1107x; 1.1107x over previous
#include <cuda_runtime.h>
#include <cuda_bf16.h>
#include <cstdint>

#define DD 2048
#define BB 256
#define TT 64

// scratch (static device arrays — no allocations)
__device__ float          g_u [BB * DD];   // 2 MB: u = E@(W-I) + E + hb
__device__ __nv_bfloat16  g_Eh[BB * DD];   // 1 MB: bf16(E)

// ---------------------------------------------------------------------------
// Kernel 0: E -> bf16 (tiny: 2 MB read, 1 MB write)
// ---------------------------------------------------------------------------
__global__ __launch_bounds__(512) void convE_kernel(const float* __restrict__ E)
{
    const int j = blockIdx.x * 512 + threadIdx.x;   // 65536 jobs of 8 floats
    float4 a = reinterpret_cast<const float4*>(E)[j * 2];
    float4 b = reinterpret_cast<const float4*>(E)[j * 2 + 1];
    __nv_bfloat162 p0 = __floats2bfloat162_rn(a.x, a.y);
    __nv_bfloat162 p1 = __floats2bfloat162_rn(a.z, a.w);
    __nv_bfloat162 p2 = __floats2bfloat162_rn(b.x, b.y);
    __nv_bfloat162 p3 = __floats2bfloat162_rn(b.z, b.w);
    uint4 o;
    o.x = *reinterpret_cast<uint32_t*>(&p0);
    o.y = *reinterpret_cast<uint32_t*>(&p1);
    o.z = *reinterpret_cast<uint32_t*>(&p2);
    o.w = *reinterpret_cast<uint32_t*>(&p3);
    reinterpret_cast<uint4*>(g_Eh)[j] = o;
}

// ---------------------------------------------------------------------------
// helpers
// ---------------------------------------------------------------------------
__device__ __forceinline__ void mma16816(float* d, const uint32_t* a,
                                         uint32_t b0, uint32_t b1)
{
    asm volatile(
        "mma.sync.aligned.m16n8k16.row.col.f32.bf16.bf16.f32 "
        "{%0,%1,%2,%3}, {%4,%5,%6,%7}, {%8,%9}, {%0,%1,%2,%3};\n"
        : "+f"(d[0]), "+f"(d[1]), "+f"(d[2]), "+f"(d[3])
        : "r"(a[0]), "r"(a[1]), "r"(a[2]), "r"(a[3]), "r"(b0), "r"(b1));
}
__device__ __forceinline__ void ldsm_x4(uint32_t* r, uint32_t addr)
{
    asm volatile("ldmatrix.sync.aligned.m8n8.x4.shared.b16 {%0,%1,%2,%3}, [%4];\n"
                 : "=r"(r[0]), "=r"(r[1]), "=r"(r[2]), "=r"(r[3]) : "r"(addr));
}
__device__ __forceinline__ void ldsm_x4_t(uint32_t* r, uint32_t addr)
{
    asm volatile("ldmatrix.sync.aligned.m8n8.x4.trans.shared.b16 {%0,%1,%2,%3}, [%4];\n"
                 : "=r"(r[0]), "=r"(r[1]), "=r"(r[2]), "=r"(r[3]) : "r"(addr));
}
__device__ __forceinline__ void cp16(uint32_t saddr, const void* gaddr)
{
    asm volatile("cp.async.cg.shared.global [%0], [%1], 16;\n"
                 :: "r"(saddr), "l"(gaddr) : "memory");
}
__device__ __forceinline__ void lds128f(float4& v, uint32_t addr)
{
    asm volatile("ld.shared.v4.f32 {%0,%1,%2,%3}, [%4];\n"
                 : "=f"(v.x), "=f"(v.y), "=f"(v.z), "=f"(v.w) : "r"(addr));
}
__device__ __forceinline__ void sts128(uint32_t addr, const uint4& o)
{
    asm volatile("st.shared.v4.b32 [%0], {%1,%2,%3,%4};\n"
                 :: "r"(addr), "r"(o.x), "r"(o.y), "r"(o.z), "r"(o.w));
}
__device__ __forceinline__ uint4 pack_bf16x8(const float4& a, const float4& b)
{
    __nv_bfloat162 p0 = __floats2bfloat162_rn(a.x, a.y);
    __nv_bfloat162 p1 = __floats2bfloat162_rn(a.z, a.w);
    __nv_bfloat162 p2 = __floats2bfloat162_rn(b.x, b.y);
    __nv_bfloat162 p3 = __floats2bfloat162_rn(b.z, b.w);
    uint4 o;
    o.x = *reinterpret_cast<uint32_t*>(&p0);
    o.y = *reinterpret_cast<uint32_t*>(&p1);
    o.z = *reinterpret_cast<uint32_t*>(&p2);
    o.w = *reinterpret_cast<uint32_t*>(&p3);
    return o;
}

// ---------------------------------------------------------------------------
// Fused GEMM: U = bf16(E) @ bf16(W - I) + E + hb
// A: cp.async bf16 from g_Eh (double-buffered, swizzled).
// B: cp.async fp32 W tile into padded smem (288B rows, double-buffered),
//    converted in-kernel (LDS.128 -> diag-fix -> cvt -> swizzled STS.128).
// Per iter: wait g(it); bar1; issue g(it+1); convert B; bar2; mma.
// Dynamic smem: As bf16 2x8K | Bs bf16 8K | Bf32 2x18K  = 60 KB
// ---------------------------------------------------------------------------
__global__ __launch_bounds__(256) void gemm_u_kernel(
    const float* __restrict__ E, const float* __restrict__ W,
    const float* __restrict__ hb)
{
    extern __shared__ __align__(1024) char smem[];
    const uint32_t base = (uint32_t)__cvta_generic_to_shared(smem);
    const uint32_t sA0 = base;               // 8 KB
    const uint32_t sA1 = base + 8192;        // 8 KB
    const uint32_t sBs = base + 16384;       // 8 KB bf16 B (single)
    const uint32_t sF0 = base + 24576;       // 18 KB fp32 B stage 0
    const uint32_t sF1 = base + 24576 + 18432;

    const int tid  = threadIdx.x;
    const int lane = tid & 31;
    const int wid  = tid >> 5;
    const int wm   = (wid >> 2) << 5;
    const int wn   = (wid & 3) << 4;
    const int bm   = blockIdx.y << 6;
    const int bn   = blockIdx.x << 6;

    float acc[2][2][4];
    #pragma unroll
    for (int i = 0; i < 2; i++)
        #pragma unroll
        for (int j = 0; j < 2; j++)
            #pragma unroll
            for (int k = 0; k < 4; k++) acc[i][j][k] = 0.f;

    // A cp.async mapping (bf16, swizzled 128B rows): 2 chunks/thread
    const int rA = tid >> 3;                 // 0..31 (+32)
    const int cA = tid & 7;
    const uint32_t offA0 = (uint32_t)((rA << 7) + ((cA ^ (rA & 7)) << 4));
    const uint32_t offA1 = offA0 + (32 << 7);
    const __nv_bfloat16* gA0 = g_Eh + (size_t)(bm + rA) * DD + cA * 8;
    const __nv_bfloat16* gA1 = gA0 + (size_t)32 * DD;

    // B fp32 cp.async mapping: 4 chunks/thread into 288B-padded rows
    int  fRow[4]; uint32_t fOff[4];
    #pragma unroll
    for (int j = 0; j < 4; j++) {
        int c = tid + 256 * j;
        fRow[j] = c >> 4;
        fOff[j] = (uint32_t)(fRow[j] * 288 + (c & 15) * 16);
    }
    const float* gBbase = W + bn;

    // B convert mapping: rows rA, rA+32; 8 floats at col cA*8
    const uint32_t cvIn0  = (uint32_t)(rA * 288 + cA * 32);
    const uint32_t cvIn1  = cvIn0 + 32 * 288;
    const uint32_t cvOut0 = offA0;           // same swizzle formula
    const uint32_t cvOut1 = offA1;

    // ldmatrix addressing
    const int l15 = lane & 15;
    const int l7  = lane & 7;
    const int kcB = lane >> 4;
    uint32_t aRow[2];
    #pragma unroll
    for (int im = 0; im < 2; im++) aRow[im] = (uint32_t)((wm + im * 16 + l15) << 7);
    const int nChunkBase = wn >> 3;

    #define ISSUE_GROUP(sa, sf, k0)                                         \
        {                                                                   \
            cp16((sa) + offA0, gA0 + (k0));                                 \
            cp16((sa) + offA1, gA1 + (k0));                                 \
            _Pragma("unroll")                                               \
            for (int j = 0; j < 4; j++)                                     \
                cp16((sf) + fOff[j],                                        \
                     gBbase + (size_t)((k0) + fRow[j]) * DD + ((tid + 256 * j) & 15) * 4); \
            asm volatile("cp.async.commit_group;\n" ::: "memory");          \
        }

    ISSUE_GROUP(sA0, sF0, 0);

    const int NIT = DD / 64;   // 32
    for (int it = 0; it < NIT; it++) {
        const int s  = it & 1;
        const int k0 = it * 64;
        const uint32_t sAc = s ? sA1 : sA0;
        const uint32_t sFc = s ? sF1 : sF0;

        asm volatile("cp.async.wait_group 0;\n" ::: "memory");
        __syncthreads();                               // bar1

        if (it + 1 < NIT) {
            const uint32_t sAn = s ? sA0 : sA1;
            const uint32_t sFn = s ? sF0 : sF1;
            ISSUE_GROUP(sAn, sFn, k0 + 64);
        }

        // convert B fp32 -> bf16 (diag fix), swizzled STS
        {
            float4 f0a, f0b, f1a, f1b;
            lds128f(f0a, sFc + cvIn0);
            lds128f(f0b, sFc + cvIn0 + 16);
            lds128f(f1a, sFc + cvIn1);
            lds128f(f1b, sFc + cvIn1 + 16);
            int d0 = (k0 + rA) - (bn + cA * 8);
            if (d0 >= 0 && d0 < 4)      reinterpret_cast<float*>(&f0a)[d0]     -= 1.0f;
            else if (d0 >= 4 && d0 < 8) reinterpret_cast<float*>(&f0b)[d0 - 4] -= 1.0f;
            int d1 = d0 + 32;
            if (d1 >= 0 && d1 < 4)      reinterpret_cast<float*>(&f1a)[d1]     -= 1.0f;
            else if (d1 >= 4 && d1 < 8) reinterpret_cast<float*>(&f1b)[d1 - 4] -= 1.0f;
            sts128(sBs + cvOut0, pack_bf16x8(f0a, f0b));
            sts128(sBs + cvOut1, pack_bf16x8(f1a, f1b));
        }
        __syncthreads();                               // bar2

        #pragma unroll
        for (int kk = 0; kk < 4; kk++) {
            uint32_t a[2][4], b[4];
            const int kchunk = kk * 2 + kcB;
            #pragma unroll
            for (int im = 0; im < 2; im++)
                ldsm_x4(a[im], sAc + aRow[im] + (uint32_t)((kchunk ^ l7) << 4));
            {
                const int krow = kk * 16 + l15;
                const int nchunk = nChunkBase + kcB;
                ldsm_x4_t(b, sBs + (uint32_t)(krow << 7)
                               + (uint32_t)((nchunk ^ (krow & 7)) << 4));
            }
            #pragma unroll
            for (int im = 0; im < 2; im++) {
                mma16816(acc[im][0], a[im], b[0], b[1]);
                mma16816(acc[im][1], a[im], b[2], b[3]);
            }
        }
    }
    #undef ISSUE_GROUP

    // epilogue: u = acc + E (exact identity) + hb
    #pragma unroll
    for (int im = 0; im < 2; im++) {
        const int row0e = bm + wm + im * 16 + (lane >> 2);
        #pragma unroll
        for (int in = 0; in < 2; in++) {
            const int col = bn + wn + in * 8 + ((lane & 3) << 1);
            const float h0 = hb[col], h1 = hb[col + 1];
            g_u[(size_t)row0e * DD + col]
                = acc[im][in][0] + E[(size_t)row0e * DD + col] + h0;
            g_u[(size_t)row0e * DD + col + 1]
                = acc[im][in][1] + E[(size_t)row0e * DD + col + 1] + h1;
            g_u[(size_t)(row0e + 8) * DD + col]
                = acc[im][in][2] + E[(size_t)(row0e + 8) * DD + col] + h0;
            g_u[(size_t)(row0e + 8) * DD + col + 1]
                = acc[im][in][3] + E[(size_t)(row0e + 8) * DD + col + 1] + h1;
        }
    }
}

// ---------------------------------------------------------------------------
// Kernel B: scoring. grid (256, 4), 256 threads (8 warps). CTA (b,tc) covers
// 16 t-rows; warp w -> rows tc*16 + w*2 (+1). __ldcs on theo stream.
// ---------------------------------------------------------------------------
__global__ __launch_bounds__(256) void score_kernel(
    const float* __restrict__ E,
    const float* __restrict__ theo,
    const float* __restrict__ cand,
    const float* __restrict__ vb,
    float* __restrict__ out)
{
    const int b    = blockIdx.x;
    const int tc   = blockIdx.y;       // 0..3
    const int tid  = threadIdx.x;
    const int lane = tid & 31;
    const int wid  = tid >> 5;         // 0..7

    __shared__ float u_s[DD];
    __shared__ float red[16];
    __shared__ float s_vb, s_pos;

    float pv = 0.f, pp = 0.f;
    #pragma unroll
    for (int h = 0; h < 2; h++) {
        const int i = h * 1024 + tid * 4;
        float4 u4 = *reinterpret_cast<const float4*>(&g_u[(size_t)b * DD + i]);
        *reinterpret_cast<float4*>(&u_s[i]) = u4;
        float4 e4 = *reinterpret_cast<const float4*>(&E[(size_t)b * DD + i]);
        float4 v4 = *reinterpret_cast<const float4*>(&vb[i]);
        pv += e4.x * v4.x + e4.y * v4.y + e4.z * v4.z + e4.w * v4.w;
        if (tc == 0) {
            float4 c4 = *reinterpret_cast<const float4*>(&cand[(size_t)b * DD + i]);
            pp += u4.x * c4.x + u4.y * c4.y + u4.z * c4.z + u4.w * c4.w;
        }
    }
    #pragma unroll
    for (int o = 16; o > 0; o >>= 1) {
        pv += __shfl_xor_sync(0xFFFFFFFFu, pv, o);
        pp += __shfl_xor_sync(0xFFFFFFFFu, pp, o);
    }
    if (lane == 0) { red[wid] = pv; red[8 + wid] = pp; }
    __syncthreads();
    if (tid == 0) {
        float v = 0.f, p = 0.f;
        #pragma unroll
        for (int w = 0; w < 8; w++) { v += red[w]; p += red[8 + w]; }
        s_vb  = v;
        s_pos = p + v;
    }
    __syncthreads();
    const float vbb = s_vb;

    const int t0 = tc * 16 + wid * 2;
    const float4* ra  = reinterpret_cast<const float4*>(&theo[((size_t)b * TT + t0) * DD]);
    const float4* rb  = ra + DD / 4;
    const float4* u4p = reinterpret_cast<const float4*>(u_s);

    float s0 = 0.f, s1 = 0.f;
    #pragma unroll 4
    for (int i = lane; i < DD / 4; i += 32) {
        float4 x = __ldcs(&ra[i]);
        float4 y = __ldcs(&rb[i]);
        float4 u = u4p[i];
        s0 += x.x * u.x + x.y * u.y + x.z * u.z + x.w * u.w;
        s1 += y.x * u.x + y.y * u.y + y.z * u.z + y.w * u.w;
    }
    #pragma unroll
    for (int o = 16; o > 0; o >>= 1) {
        s0 += __shfl_xor_sync(0xFFFFFFFFu, s0, o);
        s1 += __shfl_xor_sync(0xFFFFFFFFu, s1, o);
    }
    if (lane == 0) {
        out[b * (TT + 1) + 1 + t0]     = s0 + vbb;
        out[b * (TT + 1) + 1 + t0 + 1] = s1 + vbb;
    }
    if (tc == 0 && tid == 0) out[b * (TT + 1)] = s_pos;
}

// ---------------------------------------------------------------------------
// launch: 0=experimental [B,D], 1=theoretical [B,T,D], 2=candidate [B,D],
//         3=W [D,D], 4=vb [D], 5=hb [D] ; out fp32 [B, 1+T]
// ---------------------------------------------------------------------------
extern "C" void kernel_launch(void* const* d_in, const int* in_sizes, int n_in,
                              void* d_out, int out_size)
{
    const float* E    = (const float*)d_in[0];
    const float* theo = (const float*)d_in[1];
    const float* cand = (const float*)d_in[2];
    const float* W    = (const float*)d_in[3];
    const float* vb   = (const float*)d_in[4];
    const float* hb   = (const float*)d_in[5];
    float*       out  = (float*)d_out;

    const int SMEM = 24576 + 2 * 18432;   // 61440 B
    cudaFuncSetAttribute(gemm_u_kernel,
                         cudaFuncAttributeMaxDynamicSharedMemorySize, SMEM);

    convE_kernel<<<BB * DD / 8 / 512, 512>>>(E);
    gemm_u_kernel<<<dim3(DD / 64, BB / 64), 256, SMEM>>>(E, W, hb);
    score_kernel<<<dim3(BB, 4), 256>>>(E, theo, cand, vb, out);
}

// round 6
// speedup vs baseline: 1.2865x; 1.1583x over previous
#include <cuda_runtime.h>
#include <cuda_bf16.h>
#include <cstdint>

#define DD 2048
#define BB 256
#define TT 64

// scratch (static device arrays — no allocations)
__device__ float          g_u [BB * DD];   // 2 MB: u = E@(W-I) + E + hb
__device__ __nv_bfloat16  g_Eh[BB * DD];   // 1 MB
__device__ __nv_bfloat16  g_Wh[DD * DD];   // 8 MB: bf16(W - I)

// ---------------------------------------------------------------------------
// Kernel 0: convert.  1 thread = 2 consecutive float4 -> one uint4 (16B) store.
// W pairs first (diag fix), then E pairs.  Grid covers work exactly.
// ---------------------------------------------------------------------------
__global__ __launch_bounds__(256) void convert_kernel(
    const float* __restrict__ E, const float* __restrict__ W)
{
    const int NWP = DD * DD / 8;              // 524288 W pairs
    const int j = blockIdx.x * 256 + threadIdx.x;
    if (j < NWP) {
        float4 a = reinterpret_cast<const float4*>(W)[j * 2];
        float4 b = reinterpret_cast<const float4*>(W)[j * 2 + 1];
        const int fbase = j * 8;
        const int r = fbase >> 11;            // W row
        const int d = r - (fbase & (DD - 1)); // diag offset within the 8 floats
        if (d >= 0 && d < 4)      reinterpret_cast<float*>(&a)[d]     -= 1.0f;
        else if (d >= 4 && d < 8) reinterpret_cast<float*>(&b)[d - 4] -= 1.0f;
        __nv_bfloat162 p0 = __floats2bfloat162_rn(a.x, a.y);
        __nv_bfloat162 p1 = __floats2bfloat162_rn(a.z, a.w);
        __nv_bfloat162 p2 = __floats2bfloat162_rn(b.x, b.y);
        __nv_bfloat162 p3 = __floats2bfloat162_rn(b.z, b.w);
        uint4 o;
        o.x = *reinterpret_cast<uint32_t*>(&p0);
        o.y = *reinterpret_cast<uint32_t*>(&p1);
        o.z = *reinterpret_cast<uint32_t*>(&p2);
        o.w = *reinterpret_cast<uint32_t*>(&p3);
        reinterpret_cast<uint4*>(g_Wh)[j] = o;
    } else {
        const int k = j - NWP;                // E pair
        float4 a = reinterpret_cast<const float4*>(E)[k * 2];
        float4 b = reinterpret_cast<const float4*>(E)[k * 2 + 1];
        __nv_bfloat162 p0 = __floats2bfloat162_rn(a.x, a.y);
        __nv_bfloat162 p1 = __floats2bfloat162_rn(a.z, a.w);
        __nv_bfloat162 p2 = __floats2bfloat162_rn(b.x, b.y);
        __nv_bfloat162 p3 = __floats2bfloat162_rn(b.z, b.w);
        uint4 o;
        o.x = *reinterpret_cast<uint32_t*>(&p0);
        o.y = *reinterpret_cast<uint32_t*>(&p1);
        o.z = *reinterpret_cast<uint32_t*>(&p2);
        o.w = *reinterpret_cast<uint32_t*>(&p3);
        reinterpret_cast<uint4*>(g_Eh)[k] = o;
    }
}

// ---------------------------------------------------------------------------
// Kernel A: tensor-core GEMM  U = Eh @ Wh + E + hb   (round-3 proven version)
// ---------------------------------------------------------------------------
__device__ __forceinline__ void mma16816(float* d, const uint32_t* a,
                                         uint32_t b0, uint32_t b1)
{
    asm volatile(
        "mma.sync.aligned.m16n8k16.row.col.f32.bf16.bf16.f32 "
        "{%0,%1,%2,%3}, {%4,%5,%6,%7}, {%8,%9}, {%0,%1,%2,%3};\n"
        : "+f"(d[0]), "+f"(d[1]), "+f"(d[2]), "+f"(d[3])
        : "r"(a[0]), "r"(a[1]), "r"(a[2]), "r"(a[3]), "r"(b0), "r"(b1));
}
__device__ __forceinline__ void ldsm_x4(uint32_t* r, uint32_t addr)
{
    asm volatile("ldmatrix.sync.aligned.m8n8.x4.shared.b16 {%0,%1,%2,%3}, [%4];\n"
                 : "=r"(r[0]), "=r"(r[1]), "=r"(r[2]), "=r"(r[3]) : "r"(addr));
}
__device__ __forceinline__ void ldsm_x4_t(uint32_t* r, uint32_t addr)
{
    asm volatile("ldmatrix.sync.aligned.m8n8.x4.trans.shared.b16 {%0,%1,%2,%3}, [%4];\n"
                 : "=r"(r[0]), "=r"(r[1]), "=r"(r[2]), "=r"(r[3]) : "r"(addr));
}
__device__ __forceinline__ void cp16(uint32_t saddr, const void* gaddr)
{
    asm volatile("cp.async.cg.shared.global [%0], [%1], 16;\n"
                 :: "r"(saddr), "l"(gaddr) : "memory");
}

__global__ __launch_bounds__(256) void gemm_u_kernel(
    const float* __restrict__ E, const float* __restrict__ hb)
{
    __shared__ __align__(1024) __nv_bfloat16 As[2][64 * 64];
    __shared__ __align__(1024) __nv_bfloat16 Bs[2][64 * 64];

    const int tid  = threadIdx.x;
    const int lane = tid & 31;
    const int wid  = tid >> 5;
    const int wm   = (wid >> 2) << 5;
    const int wn   = (wid & 3) << 4;
    const int bm   = blockIdx.y << 6;
    const int bn   = blockIdx.x << 6;

    float acc[2][2][4];
    #pragma unroll
    for (int i = 0; i < 2; i++)
        #pragma unroll
        for (int j = 0; j < 2; j++)
            #pragma unroll
            for (int k = 0; k < 4; k++) acc[i][j][k] = 0.f;

    const int r0 = tid >> 3;
    const int c0 = tid & 7;
    const uint32_t swzOff  = (uint32_t)((r0 << 7) + ((c0 ^ (r0 & 7)) << 4));
    const uint32_t swzOff2 = swzOff + (32 << 7);

    uint32_t sA[2], sB[2];
    sA[0] = (uint32_t)__cvta_generic_to_shared(&As[0][0]);
    sA[1] = (uint32_t)__cvta_generic_to_shared(&As[1][0]);
    sB[0] = (uint32_t)__cvta_generic_to_shared(&Bs[0][0]);
    sB[1] = (uint32_t)__cvta_generic_to_shared(&Bs[1][0]);

    const __nv_bfloat16* gA  = g_Eh + (size_t)(bm + r0) * DD + c0 * 8;
    const __nv_bfloat16* gA2 = gA + (size_t)32 * DD;
    const __nv_bfloat16* gB  = g_Wh + (size_t)r0 * DD + bn + c0 * 8;
    const __nv_bfloat16* gB2 = gB + (size_t)32 * DD;

    const int l15 = lane & 15;
    const int l7  = lane & 7;
    const int kcB = lane >> 4;
    uint32_t aRow[2];
    #pragma unroll
    for (int im = 0; im < 2; im++) aRow[im] = (uint32_t)((wm + im * 16 + l15) << 7);
    const int nChunkBase = wn >> 3;

    #define LOAD_TILES(s, k0)                                              \
        {                                                                  \
            cp16(sA[s] + swzOff,  gA  + (k0));                             \
            cp16(sA[s] + swzOff2, gA2 + (k0));                             \
            cp16(sB[s] + swzOff,  gB  + (size_t)(k0) * DD);                \
            cp16(sB[s] + swzOff2, gB2 + (size_t)(k0) * DD);                \
            asm volatile("cp.async.commit_group;\n" ::: "memory");         \
        }

    LOAD_TILES(0, 0);

    const int NIT = DD / 64;
    for (int it = 0; it < NIT; it++) {
        const int s = it & 1;
        if (it + 1 < NIT) {
            LOAD_TILES(s ^ 1, (it + 1) * 64);
            asm volatile("cp.async.wait_group 1;\n" ::: "memory");
        } else {
            asm volatile("cp.async.wait_group 0;\n" ::: "memory");
        }
        __syncthreads();

        #pragma unroll
        for (int kk = 0; kk < 4; kk++) {
            uint32_t a[2][4], b[4];
            const int kchunk = kk * 2 + kcB;
            #pragma unroll
            for (int im = 0; im < 2; im++)
                ldsm_x4(a[im], sA[s] + aRow[im] + (uint32_t)((kchunk ^ l7) << 4));
            {
                const int krow = kk * 16 + l15;
                const int nchunk = nChunkBase + kcB;
                ldsm_x4_t(b, sB[s] + (uint32_t)(krow << 7)
                               + (uint32_t)((nchunk ^ (krow & 7)) << 4));
            }
            #pragma unroll
            for (int im = 0; im < 2; im++) {
                mma16816(acc[im][0], a[im], b[0], b[1]);
                mma16816(acc[im][1], a[im], b[2], b[3]);
            }
        }
        __syncthreads();
    }
    #undef LOAD_TILES

    #pragma unroll
    for (int im = 0; im < 2; im++) {
        const int row0e = bm + wm + im * 16 + (lane >> 2);
        #pragma unroll
        for (int in = 0; in < 2; in++) {
            const int col = bn + wn + in * 8 + ((lane & 3) << 1);
            const float h0 = hb[col], h1 = hb[col + 1];
            g_u[(size_t)row0e * DD + col]
                = acc[im][in][0] + E[(size_t)row0e * DD + col] + h0;
            g_u[(size_t)row0e * DD + col + 1]
                = acc[im][in][1] + E[(size_t)row0e * DD + col + 1] + h1;
            g_u[(size_t)(row0e + 8) * DD + col]
                = acc[im][in][2] + E[(size_t)(row0e + 8) * DD + col] + h0;
            g_u[(size_t)(row0e + 8) * DD + col + 1]
                = acc[im][in][3] + E[(size_t)(row0e + 8) * DD + col + 1] + h1;
        }
    }
}

// ---------------------------------------------------------------------------
// Kernel B: scoring with cp.async-pipelined theoretical stream.
// grid (256, 4), 256 threads (8 warps). CTA (b, tc): 16 t-rows (tc*16..+15).
// theo streamed in 16 stages of [16 rows x 128 cols] fp32 (8 KB), 3 buffers,
// 2 stages in flight -> in-flight bytes live in smem, not registers.
//   vb_b = dot(E[b], vb) ; pos = dot(u[b], cand[b]) + vb_b (cand@hb cancels)
//   neg[t] = dot(theo[b,t], u[b]) + vb_b
// ---------------------------------------------------------------------------
__global__ __launch_bounds__(256) void score_kernel(
    const float* __restrict__ E,
    const float* __restrict__ theo,
    const float* __restrict__ cand,
    const float* __restrict__ vb,
    float* __restrict__ out)
{
    const int b    = blockIdx.x;
    const int tc   = blockIdx.y;       // 0..3
    const int tid  = threadIdx.x;
    const int lane = tid & 31;
    const int wid  = tid >> 5;         // 0..7

    __shared__ float u_s[DD];                  // 8 KB
    __shared__ __align__(16) float thS[3][16 * 128];   // 3 x 8 KB
    __shared__ float red[16];
    __shared__ float s_vb, s_pos;

    const uint32_t thSb = (uint32_t)__cvta_generic_to_shared(&thS[0][0]);

    // cp.async mapping: chunk c in [0,512): row = c>>5, 16B chunk = c&31.
    // thread t handles c = t and c = t + 256.
    const int rS0 = tid >> 5;                  // rows 0..7
    const int rS1 = rS0 + 8;                   // rows 8..15
    const int cS  = tid & 31;                  // 16B chunk in row
    const float* gT0 = theo + ((size_t)b * TT + tc * 16 + rS0) * DD + cS * 4;
    const float* gT1 = theo + ((size_t)b * TT + tc * 16 + rS1) * DD + cS * 4;
    const uint32_t sOff0 = (uint32_t)(rS0 * 512 + cS * 16);
    const uint32_t sOff1 = (uint32_t)(rS1 * 512 + cS * 16);

    #define ISSUE_STAGE(st)                                                 \
        {                                                                   \
            const uint32_t sb = thSb + (uint32_t)(((st) % 3) * 8192);       \
            const int k0 = (st) * 128;                                      \
            asm volatile("cp.async.cg.shared.global [%0], [%1], 16;\n"      \
                         :: "r"(sb + sOff0), "l"(gT0 + k0) : "memory");     \
            asm volatile("cp.async.cg.shared.global [%0], [%1], 16;\n"      \
                         :: "r"(sb + sOff1), "l"(gT1 + k0) : "memory");     \
            asm volatile("cp.async.commit_group;\n" ::: "memory");          \
        }

    ISSUE_STAGE(0);
    ISSUE_STAGE(1);

    // preamble (overlaps with the first cp.async stages):
    // stage u[b] into smem; block-reduce vb-dot and pos-dot
    float pv = 0.f, pp = 0.f;
    #pragma unroll
    for (int h = 0; h < 2; h++) {
        const int i = h * 1024 + tid * 4;
        float4 u4 = *reinterpret_cast<const float4*>(&g_u[(size_t)b * DD + i]);
        *reinterpret_cast<float4*>(&u_s[i]) = u4;
        float4 e4 = *reinterpret_cast<const float4*>(&E[(size_t)b * DD + i]);
        float4 v4 = *reinterpret_cast<const float4*>(&vb[i]);
        pv += e4.x * v4.x + e4.y * v4.y + e4.z * v4.z + e4.w * v4.w;
        if (tc == 0) {
            float4 c4 = *reinterpret_cast<const float4*>(&cand[(size_t)b * DD + i]);
            pp += u4.x * c4.x + u4.y * c4.y + u4.z * c4.z + u4.w * c4.w;
        }
    }
    #pragma unroll
    for (int o = 16; o > 0; o >>= 1) {
        pv += __shfl_xor_sync(0xFFFFFFFFu, pv, o);
        pp += __shfl_xor_sync(0xFFFFFFFFu, pp, o);
    }
    if (lane == 0) { red[wid] = pv; red[8 + wid] = pp; }
    __syncthreads();
    if (tid == 0) {
        float v = 0.f, p = 0.f;
        #pragma unroll
        for (int w = 0; w < 8; w++) { v += red[w]; p += red[8 + w]; }
        s_vb  = v;
        s_pos = p + v;
    }

    // mainloop: warp w computes local rows 2w, 2w+1
    const int rl0 = wid * 2;
    const int rl1 = rl0 + 1;
    float s0 = 0.f, s1 = 0.f;

    const int NST = DD / 128;   // 16
    for (int st = 0; st < NST; st++) {
        if (st + 1 < NST)
            asm volatile("cp.async.wait_group 1;\n" ::: "memory");
        else
            asm volatile("cp.async.wait_group 0;\n" ::: "memory");
        __syncthreads();

        if (st + 2 < NST) ISSUE_STAGE(st + 2);

        const float* buf = &thS[st % 3][0];
        const int k0 = st * 128;
        float4 x = *reinterpret_cast<const float4*>(&buf[rl0 * 128 + lane * 4]);
        float4 y = *reinterpret_cast<const float4*>(&buf[rl1 * 128 + lane * 4]);
        float4 u = *reinterpret_cast<const float4*>(&u_s[k0 + lane * 4]);
        s0 += x.x * u.x + x.y * u.y + x.z * u.z + x.w * u.w;
        s1 += y.x * u.x + y.y * u.y + y.z * u.z + y.w * u.w;
    }
    #undef ISSUE_STAGE

    #pragma unroll
    for (int o = 16; o > 0; o >>= 1) {
        s0 += __shfl_xor_sync(0xFFFFFFFFu, s0, o);
        s1 += __shfl_xor_sync(0xFFFFFFFFu, s1, o);
    }
    const float vbb = s_vb;
    if (lane == 0) {
        const int t0 = tc * 16 + rl0;
        out[b * (TT + 1) + 1 + t0]     = s0 + vbb;
        out[b * (TT + 1) + 1 + t0 + 1] = s1 + vbb;
    }
    if (tc == 0 && tid == 0) out[b * (TT + 1)] = s_pos;
}

// ---------------------------------------------------------------------------
// launch: 0=experimental [B,D], 1=theoretical [B,T,D], 2=candidate [B,D],
//         3=W [D,D], 4=vb [D], 5=hb [D] ; out fp32 [B, 1+T]
// ---------------------------------------------------------------------------
extern "C" void kernel_launch(void* const* d_in, const int* in_sizes, int n_in,
                              void* d_out, int out_size)
{
    const float* E    = (const float*)d_in[0];
    const float* theo = (const float*)d_in[1];
    const float* cand = (const float*)d_in[2];
    const float* W    = (const float*)d_in[3];
    const float* vb   = (const float*)d_in[4];
    const float* hb   = (const float*)d_in[5];
    float*       out  = (float*)d_out;

    const int npairs = DD * DD / 8 + BB * DD / 8;   // 589824
    convert_kernel<<<npairs / 256, 256>>>(E, W);
    gemm_u_kernel<<<dim3(DD / 64, BB / 64), 256>>>(E, hb);
    score_kernel<<<dim3(BB, 4), 256>>>(E, theo, cand, vb, out);
}